// round 2
// baseline (speedup 1.0000x reference)
#include <cuda_runtime.h>
#include <cstddef>

// Problem constants
#define BB   32
#define TT   1024
#define CC   512
#define KK   3
#define LMAX 4096
#define BT   (BB*TT)
#define LN_EPS 1e-5f

// ---------------- scratch (device globals; no allocations allowed) ----------
__device__ float g_buf1[(size_t)BT * CC];          // conv1 out -> LN in-place -> conv2 in
__device__ float g_buf2[(size_t)BT * CC];          // conv2 out
__device__ float g_wt[2 * KK * CC * CC];           // transposed weights [set][k][ci][co]
__device__ int   g_cum[BB * TT];                   // inclusive cumsum of durations

// ---------------- weight transpose: w[co][ci][k] -> wt[k][ci][co] ----------
__global__ void __launch_bounds__(256) wt_kernel(const float* __restrict__ w,
                                                 float* __restrict__ wt)
{
    int idx = blockIdx.x * 256 + threadIdx.x;      // over CC*CC
    if (idx >= CC * CC) return;
    int co = idx >> 9;
    int ci = idx & (CC - 1);
#pragma unroll
    for (int k = 0; k < KK; k++)
        wt[((size_t)k * CC + ci) * CC + co] = w[((size_t)co * CC + ci) * KK + k];
}

// ---------------- durations: mask, total==0 fallback, inclusive scan --------
__global__ void __launch_bounds__(256) dur_kernel(const int* __restrict__ durs,
                                                  const int* __restrict__ lens,
                                                  int* __restrict__ cum,
                                                  float* __restrict__ mel)
{
    int b   = blockIdx.x;
    int len = lens[b];
    int tid = threadIdx.x;
    int base = tid * 4;
    const int* drow = durs + (size_t)b * TT;

    int d[4];
#pragma unroll
    for (int j = 0; j < 4; j++)
        d[j] = (base + j < len) ? drow[base + j] : 0;
    int ls = d[0] + d[1] + d[2] + d[3];

    __shared__ int sred[256];
    sred[tid] = ls;
    __syncthreads();
    for (int o = 128; o > 0; o >>= 1) {
        if (tid < o) sred[tid] += sred[tid + o];
        __syncthreads();
    }
    int total = sred[0];
    __syncthreads();

    if (total == 0) {   // torch fallback: durations of 1 on valid tokens
#pragma unroll
        for (int j = 0; j < 4; j++)
            d[j] = (base + j < len) ? 1 : 0;
        ls = d[0] + d[1] + d[2] + d[3];
    }

    // block scan of per-thread sums (Hillis-Steele)
    __shared__ int sscan[256];
    sscan[tid] = ls;
    __syncthreads();
    for (int o = 1; o < 256; o <<= 1) {
        int v = (tid >= o) ? sscan[tid - o] : 0;
        __syncthreads();
        sscan[tid] += v;
        __syncthreads();
    }
    int c = sscan[tid] - ls;   // exclusive prefix
#pragma unroll
    for (int j = 0; j < 4; j++) {
        c += d[j];
        cum[(size_t)b * TT + base + j] = c;
    }
    if (tid == 255) mel[b] = (float)c;   // c == total (post-fallback)
}

// ---------------- conv-as-GEMM: out[m,n] = sum_k sum_ci A[m+k-1,ci]*Wt[k][ci][n]
// 64x64 block tile, 256 threads, 4x4 per thread, fp32. ReLU+bias fused.
__global__ void __launch_bounds__(256) conv_gemm_kernel(const float* __restrict__ A,
                                                        const float* __restrict__ Wt,
                                                        const float* __restrict__ bias,
                                                        float* __restrict__ out)
{
    __shared__ float As[64][17];                       // [row][ci] (+1 pad)
    __shared__ __align__(16) float Ws[16][68];         // [ci][co]  (+4 pad, 16B aligned rows)

    int m0 = blockIdx.x * 64;
    int n0 = blockIdx.y * 64;
    int b  = m0 >> 10;           // T = 1024
    int t0 = m0 & 1023;
    int tid = threadIdx.x;
    int ty = tid >> 4;           // 0..15
    int tx = tid & 15;           // 0..15

    float acc[4][4];
#pragma unroll
    for (int i = 0; i < 4; i++)
#pragma unroll
        for (int j = 0; j < 4; j++) acc[i][j] = 0.f;

    int a_r = tid >> 2;          // 0..63
    int a_c = (tid & 3) * 4;     // 0,4,8,12
    int w_r = tid >> 4;          // 0..15
    int w_c = (tid & 15) * 4;    // 0..60

    const float* Abase = A + (size_t)b * TT * CC;

    for (int kk = 0; kk < KK * CC; kk += 16) {
        int k   = kk >> 9;
        int ci0 = kk & (CC - 1);

        // A tile (shift by k-1, zero outside [0,T))
        int st = t0 + a_r + k - 1;
        float4 av = make_float4(0.f, 0.f, 0.f, 0.f);
        if (st >= 0 && st < TT)
            av = *(const float4*)(Abase + (size_t)st * CC + ci0 + a_c);
        As[a_r][a_c + 0] = av.x;
        As[a_r][a_c + 1] = av.y;
        As[a_r][a_c + 2] = av.z;
        As[a_r][a_c + 3] = av.w;

        // W tile
        float4 wv = *(const float4*)(Wt + (size_t)(kk + w_r) * CC + n0 + w_c);
        *(float4*)&Ws[w_r][w_c] = wv;

        __syncthreads();
#pragma unroll
        for (int p = 0; p < 16; p++) {
            float a0 = As[ty * 4 + 0][p];
            float a1 = As[ty * 4 + 1][p];
            float a2 = As[ty * 4 + 2][p];
            float a3 = As[ty * 4 + 3][p];
            float4 bv = *(const float4*)&Ws[p][tx * 4];
            acc[0][0] += a0 * bv.x; acc[0][1] += a0 * bv.y; acc[0][2] += a0 * bv.z; acc[0][3] += a0 * bv.w;
            acc[1][0] += a1 * bv.x; acc[1][1] += a1 * bv.y; acc[1][2] += a1 * bv.z; acc[1][3] += a1 * bv.w;
            acc[2][0] += a2 * bv.x; acc[2][1] += a2 * bv.y; acc[2][2] += a2 * bv.z; acc[2][3] += a2 * bv.w;
            acc[3][0] += a3 * bv.x; acc[3][1] += a3 * bv.y; acc[3][2] += a3 * bv.z; acc[3][3] += a3 * bv.w;
        }
        __syncthreads();
    }

    float4 bz = *(const float4*)(bias + n0 + tx * 4);
#pragma unroll
    for (int i = 0; i < 4; i++) {
        int row = m0 + ty * 4 + i;
        float4 r;
        r.x = fmaxf(acc[i][0] + bz.x, 0.f);
        r.y = fmaxf(acc[i][1] + bz.y, 0.f);
        r.z = fmaxf(acc[i][2] + bz.z, 0.f);
        r.w = fmaxf(acc[i][3] + bz.w, 0.f);
        *(float4*)(out + (size_t)row * CC + n0 + tx * 4) = r;
    }
}

// ---------------- LayerNorm over C=512, in-place, one block per row ---------
__global__ void __launch_bounds__(128) ln_kernel(float* __restrict__ x,
                                                 const float* __restrict__ g,
                                                 const float* __restrict__ beta)
{
    size_t row = blockIdx.x;
    float4* xr = (float4*)(x + row * CC);
    int tid = threadIdx.x;
    float4 v = xr[tid];
    float s = v.x + v.y + v.z + v.w;
    float q = v.x * v.x + v.y * v.y + v.z * v.z + v.w * v.w;
#pragma unroll
    for (int o = 16; o > 0; o >>= 1) {
        s += __shfl_xor_sync(0xffffffffu, s, o);
        q += __shfl_xor_sync(0xffffffffu, q, o);
    }
    __shared__ float ss[4], sq[4];
    int w = tid >> 5, l = tid & 31;
    if (l == 0) { ss[w] = s; sq[w] = q; }
    __syncthreads();
    s = ss[0] + ss[1] + ss[2] + ss[3];
    q = sq[0] + sq[1] + sq[2] + sq[3];
    float mean = s * (1.f / CC);
    float var  = q * (1.f / CC) - mean * mean;
    float r = rsqrtf(var + LN_EPS);
    float4 gv = ((const float4*)g)[tid];
    float4 bv = ((const float4*)beta)[tid];
    v.x = (v.x - mean) * r * gv.x + bv.x;
    v.y = (v.y - mean) * r * gv.y + bv.y;
    v.z = (v.z - mean) * r * gv.z + bv.z;
    v.w = (v.w - mean) * r * gv.w + bv.w;
    xr[tid] = v;
}

// ---------------- LN + Linear(C->1) + mask, one block per row ---------------
__global__ void __launch_bounds__(128) ln_lin_kernel(const float* __restrict__ x,
                                                     const float* __restrict__ g,
                                                     const float* __restrict__ beta,
                                                     const float* __restrict__ lw,
                                                     const float* __restrict__ lb,
                                                     const int* __restrict__ lens,
                                                     float* __restrict__ pred)
{
    size_t row = blockIdx.x;
    const float4* xr = (const float4*)(x + row * CC);
    int tid = threadIdx.x;
    float4 v = xr[tid];
    float s = v.x + v.y + v.z + v.w;
    float q = v.x * v.x + v.y * v.y + v.z * v.z + v.w * v.w;
#pragma unroll
    for (int o = 16; o > 0; o >>= 1) {
        s += __shfl_xor_sync(0xffffffffu, s, o);
        q += __shfl_xor_sync(0xffffffffu, q, o);
    }
    __shared__ float ss[4], sq[4], sp[4];
    int w = tid >> 5, l = tid & 31;
    if (l == 0) { ss[w] = s; sq[w] = q; }
    __syncthreads();
    s = ss[0] + ss[1] + ss[2] + ss[3];
    q = sq[0] + sq[1] + sq[2] + sq[3];
    float mean = s * (1.f / CC);
    float var  = q * (1.f / CC) - mean * mean;
    float r = rsqrtf(var + LN_EPS);
    float4 gv = ((const float4*)g)[tid];
    float4 bv = ((const float4*)beta)[tid];
    float4 wv = ((const float4*)lw)[tid];
    float part = ((v.x - mean) * r * gv.x + bv.x) * wv.x
               + ((v.y - mean) * r * gv.y + bv.y) * wv.y
               + ((v.z - mean) * r * gv.z + bv.z) * wv.z
               + ((v.w - mean) * r * gv.w + bv.w) * wv.w;
#pragma unroll
    for (int o = 16; o > 0; o >>= 1)
        part += __shfl_xor_sync(0xffffffffu, part, o);
    if (l == 0) sp[w] = part;
    __syncthreads();
    if (tid == 0) {
        float val = sp[0] + sp[1] + sp[2] + sp[3] + lb[0];
        int b = (int)(row >> 10);
        int t = (int)(row & 1023);
        pred[row] = (t < lens[b]) ? val : 0.f;
    }
}

// ---------------- regulate: per-frame binary search + row copy --------------
__global__ void __launch_bounds__(256) reg_kernel(const float* __restrict__ batch,
                                                  const int* __restrict__ cum,
                                                  float* __restrict__ out)
{
    int b  = blockIdx.y;
    int f0 = blockIdx.x * 32;
    __shared__ int sc[TT];
    int tid = threadIdx.x;
    const int* crow = cum + (size_t)b * TT;
#pragma unroll
    for (int j = 0; j < 4; j++) sc[tid + 256 * j] = crow[tid + 256 * j];
    __syncthreads();
    int total = sc[TT - 1];
    int warp = tid >> 5, lane = tid & 31;
    float* outb = out + (size_t)b * LMAX * CC;
    const float* inb = batch + (size_t)b * TT * CC;
#pragma unroll
    for (int qq = 0; qq < 4; qq++) {
        int f = f0 + warp * 4 + qq;
        float4* dst = (float4*)(outb + (size_t)f * CC);
        if (f < total) {
            int lo = 0, hi = TT;         // first idx with cum[idx] > f
            while (lo < hi) {
                int mid = (lo + hi) >> 1;
                if (sc[mid] <= f) lo = mid + 1; else hi = mid;
            }
            const float4* src = (const float4*)(inb + (size_t)lo * CC);
#pragma unroll
            for (int u = 0; u < 4; u++) dst[lane + 32 * u] = src[lane + 32 * u];
        } else {
            float4 z = make_float4(0.f, 0.f, 0.f, 0.f);
#pragma unroll
            for (int u = 0; u < 4; u++) dst[lane + 32 * u] = z;
        }
    }
}

// ---------------- launch --------------------------------------------------
extern "C" void kernel_launch(void* const* d_in, const int* in_sizes, int n_in,
                              void* d_out, int out_size)
{
    const float* batch = (const float*)d_in[0];
    const int*   lens  = (const int*)d_in[1];
    /* d_in[2] = mask: ignored, recomputed from token_lengths */
    const int*   durs  = (const int*)d_in[3];
    const float* w1    = (const float*)d_in[4];
    const float* b1    = (const float*)d_in[5];
    const float* g1    = (const float*)d_in[6];
    const float* be1   = (const float*)d_in[7];
    const float* w2    = (const float*)d_in[8];
    const float* b2    = (const float*)d_in[9];
    const float* g2    = (const float*)d_in[10];
    const float* be2   = (const float*)d_in[11];
    const float* lw    = (const float*)d_in[12];
    const float* lb    = (const float*)d_in[13];

    float* out    = (float*)d_out;
    float* padded = out;                                   // [B, LMAX, C]
    float* mel    = out + (size_t)BB * LMAX * CC;          // [B]
    float* pred   = mel + BB;                              // [B, T]

    float *buf1, *buf2, *wt;
    int   *cum;
    cudaGetSymbolAddress((void**)&buf1, g_buf1);
    cudaGetSymbolAddress((void**)&buf2, g_buf2);
    cudaGetSymbolAddress((void**)&wt,   g_wt);
    cudaGetSymbolAddress((void**)&cum,  g_cum);
    float* wt2 = wt + (size_t)KK * CC * CC;

    wt_kernel<<<(CC * CC + 255) / 256, 256>>>(w1, wt);
    wt_kernel<<<(CC * CC + 255) / 256, 256>>>(w2, wt2);
    dur_kernel<<<BB, 256>>>(durs, lens, cum, mel);

    dim3 gg(BT / 64, CC / 64);
    conv_gemm_kernel<<<gg, 256>>>(batch, wt, b1, buf1);
    ln_kernel<<<BT, 128>>>(buf1, g1, be1);
    conv_gemm_kernel<<<gg, 256>>>(buf1, wt2, b2, buf2);
    ln_lin_kernel<<<BT, 128>>>(buf2, g2, be2, lw, lb, lens, pred);

    reg_kernel<<<dim3(LMAX / 32, BB), 256>>>(batch, cum, padded);
}

// round 4
// speedup vs baseline: 3.1391x; 3.1391x over previous
#include <cuda_runtime.h>
#include <cstdint>
#include <cstddef>

// Problem constants
#define BB   32
#define TT   1024
#define CC   512
#define KK   3
#define LMAX 4096
#define BT   (BB*TT)
#define LN_EPS 1e-5f

// GEMM tiling (tf32 mma.sync m16n8k8)
#define BM 128
#define BN 128
#define BK 16
#define NSLAB ((KK*CC)/BK)    // 96

// ---------------- scratch (device globals; no allocations allowed) ----------
__device__ float g_buf1[(size_t)BT * CC];
__device__ float g_buf2[(size_t)BT * CC];
__device__ float g_wt[2 * KK * CC * CC];           // [set][k][ci][co]
__device__ int   g_cum[BB * TT];

// ================= helpers ==================================================
__device__ __forceinline__ uint32_t smem_u32(const void* p) {
    uint32_t r;
    asm("{ .reg .u64 t; cvta.to.shared.u64 t, %1; cvt.u32.u64 %0, t; }"
        : "=r"(r) : "l"(p));
    return r;
}
__device__ __forceinline__ void cp_async16(uint32_t dst, const void* src, bool ok) {
    int sz = ok ? 16 : 0;
    asm volatile("cp.async.ca.shared.global [%0], [%1], 16, %2;"
                 :: "r"(dst), "l"(src), "r"(sz));
}
#define CP_COMMIT() asm volatile("cp.async.commit_group;" ::: "memory")
#define CP_WAIT1()  asm volatile("cp.async.wait_group 1;" ::: "memory")
#define CP_WAIT0()  asm volatile("cp.async.wait_group 0;" ::: "memory")

__device__ __forceinline__ uint32_t f2tf32(float f) {
    uint32_t u;
    asm("cvt.rna.tf32.f32 %0, %1;" : "=r"(u) : "f"(f));
    return u;
}
__device__ __forceinline__ void mma_tf32(float* c, const uint32_t* a, const uint32_t* b) {
    asm volatile("mma.sync.aligned.m16n8k8.row.col.f32.tf32.tf32.f32 "
                 "{%0,%1,%2,%3}, {%4,%5,%6,%7}, {%8,%9}, {%0,%1,%2,%3};"
                 : "+f"(c[0]), "+f"(c[1]), "+f"(c[2]), "+f"(c[3])
                 : "r"(a[0]), "r"(a[1]), "r"(a[2]), "r"(a[3]),
                   "r"(b[0]), "r"(b[1]));
}

// ---------------- weight transpose: w[co][ci][k] -> wt[k][ci][co] ----------
__global__ void __launch_bounds__(256) wt_kernel(const float* __restrict__ w,
                                                 float* __restrict__ wt)
{
    int idx = blockIdx.x * 256 + threadIdx.x;
    if (idx >= CC * CC) return;
    int co = idx >> 9;
    int ci = idx & (CC - 1);
#pragma unroll
    for (int k = 0; k < KK; k++)
        wt[((size_t)k * CC + ci) * CC + co] = w[((size_t)co * CC + ci) * KK + k];
}

// ---------------- durations: mask, total==0 fallback, inclusive scan --------
__global__ void __launch_bounds__(256) dur_kernel(const int* __restrict__ durs,
                                                  const int* __restrict__ lens,
                                                  int* __restrict__ cum,
                                                  float* __restrict__ mel)
{
    int b   = blockIdx.x;
    int len = lens[b];
    int tid = threadIdx.x;
    int base = tid * 4;
    const int* drow = durs + (size_t)b * TT;

    int d[4];
#pragma unroll
    for (int j = 0; j < 4; j++)
        d[j] = (base + j < len) ? drow[base + j] : 0;
    int ls = d[0] + d[1] + d[2] + d[3];

    __shared__ int sred[256];
    sred[tid] = ls;
    __syncthreads();
    for (int o = 128; o > 0; o >>= 1) {
        if (tid < o) sred[tid] += sred[tid + o];
        __syncthreads();
    }
    int total = sred[0];
    __syncthreads();

    if (total == 0) {
#pragma unroll
        for (int j = 0; j < 4; j++)
            d[j] = (base + j < len) ? 1 : 0;
        ls = d[0] + d[1] + d[2] + d[3];
    }

    __shared__ int sscan[256];
    sscan[tid] = ls;
    __syncthreads();
    for (int o = 1; o < 256; o <<= 1) {
        int v = (tid >= o) ? sscan[tid - o] : 0;
        __syncthreads();
        sscan[tid] += v;
        __syncthreads();
    }
    int c = sscan[tid] - ls;
#pragma unroll
    for (int j = 0; j < 4; j++) {
        c += d[j];
        cum[(size_t)b * TT + base + j] = c;
    }
    if (tid == 255) mel[b] = (float)c;
}

// ---------------- conv-as-GEMM on tf32 mma.sync -----------------------------
// out[m,n] = relu(sum_k sum_ci A[m+k-1,ci] * Wt[k][ci][n] + bias[n])
// 128x128 tile, BK=16 slabs, cp.async double buffer, 8 warps (warp tile 64x32).
__global__ void __launch_bounds__(256, 1) conv_mma_kernel(const float* __restrict__ A,
                                                          const float* __restrict__ Wt,
                                                          const float* __restrict__ bias,
                                                          float* __restrict__ out)
{
    __shared__ float As[2][BM][20];    // pad 20: conflict-free frag loads
    __shared__ float Bs[2][BK][132];   // pad 132: conflict-free frag loads

    int tid  = threadIdx.x;
    int wid  = tid >> 5;
    int lane = tid & 31;
    int warp_m = wid & 1;        // 2 warps in M (64 rows each)
    int warp_n = wid >> 1;       // 4 warps in N (32 cols each)
    int gid = lane >> 2;         // 0..7
    int tig = lane & 3;          // 0..3

    int m0 = blockIdx.x * BM;
    int b  = m0 >> 10;
    int t0 = m0 & 1023;
    int n0 = blockIdx.y * BN;
    const float* Ab = A + (size_t)b * TT * CC;

    // loader lanes
    int ar = tid >> 2;           // 0..63 (rows ar, ar+64)
    int ac = (tid & 3) * 4;      // 0,4,8,12
    int br = tid >> 5;           // 0..7  (rows br, br+8)
    int bc = (tid & 31) * 4;     // 0..124

    float c[4][4][4];
#pragma unroll
    for (int mt = 0; mt < 4; mt++)
#pragma unroll
        for (int nt = 0; nt < 4; nt++)
#pragma unroll
            for (int q = 0; q < 4; q++) c[mt][nt][q] = 0.f;

    // ---- slab loader ----
    auto load_slab = [&](int s, int buf) {
        int k   = s >> 5;              // 0..2  (32 slabs per conv tap)
        int ci0 = (s & 31) * BK;       // 0..496
#pragma unroll
        for (int h = 0; h < 2; h++) {
            int r = ar + h * 64;
            int strow = t0 + r + k - 1;
            bool ok = (strow >= 0 && strow < TT);
            const float* src = Ab + (ok ? (size_t)strow * CC : 0) + ci0 + ac;
            cp_async16(smem_u32(&As[buf][r][ac]), src, ok);
        }
#pragma unroll
        for (int h = 0; h < 2; h++) {
            int r = br + h * 8;
            const float* src = Wt + ((size_t)k * CC + ci0 + r) * CC + n0 + bc;
            cp_async16(smem_u32(&Bs[buf][r][bc]), src, true);
        }
    };

    load_slab(0, 0);
    CP_COMMIT();

    for (int s = 0; s < NSLAB; s++) {
        int buf = s & 1;
        if (s + 1 < NSLAB) {
            load_slab(s + 1, buf ^ 1);
            CP_COMMIT();
            CP_WAIT1();
        } else {
            CP_WAIT0();
        }
        __syncthreads();

#pragma unroll
        for (int kk = 0; kk < BK; kk += 8) {
            uint32_t af[4][4];
#pragma unroll
            for (int mt = 0; mt < 4; mt++) {
                int mr = warp_m * 64 + mt * 16;
                af[mt][0] = f2tf32(As[buf][mr + gid    ][kk + tig    ]);
                af[mt][1] = f2tf32(As[buf][mr + gid + 8][kk + tig    ]);
                af[mt][2] = f2tf32(As[buf][mr + gid    ][kk + tig + 4]);
                af[mt][3] = f2tf32(As[buf][mr + gid + 8][kk + tig + 4]);
            }
            uint32_t bf[4][2];
#pragma unroll
            for (int nt = 0; nt < 4; nt++) {
                int nc = warp_n * 32 + nt * 8 + gid;
                bf[nt][0] = f2tf32(Bs[buf][kk + tig    ][nc]);
                bf[nt][1] = f2tf32(Bs[buf][kk + tig + 4][nc]);
            }
#pragma unroll
            for (int mt = 0; mt < 4; mt++)
#pragma unroll
                for (int nt = 0; nt < 4; nt++)
                    mma_tf32(c[mt][nt], af[mt], bf[nt]);
        }
        __syncthreads();
    }

    // ---- epilogue: bias + relu, direct coalesced-quad stores ----
#pragma unroll
    for (int mt = 0; mt < 4; mt++) {
        int row = m0 + warp_m * 64 + mt * 16 + gid;
#pragma unroll
        for (int nt = 0; nt < 4; nt++) {
            int col = n0 + warp_n * 32 + nt * 8 + tig * 2;
            float b0 = __ldg(&bias[col]);
            float b1 = __ldg(&bias[col + 1]);
            float2 v0, v1;
            v0.x = fmaxf(c[mt][nt][0] + b0, 0.f);
            v0.y = fmaxf(c[mt][nt][1] + b1, 0.f);
            v1.x = fmaxf(c[mt][nt][2] + b0, 0.f);
            v1.y = fmaxf(c[mt][nt][3] + b1, 0.f);
            *(float2*)&out[(size_t)row * CC + col]       = v0;
            *(float2*)&out[(size_t)(row + 8) * CC + col] = v1;
        }
    }
}

// ---------------- LayerNorm over C=512, in-place, one block per row ---------
__global__ void __launch_bounds__(128) ln_kernel(float* __restrict__ x,
                                                 const float* __restrict__ g,
                                                 const float* __restrict__ beta)
{
    size_t row = blockIdx.x;
    float4* xr = (float4*)(x + row * CC);
    int tid = threadIdx.x;
    float4 v = xr[tid];
    float s = v.x + v.y + v.z + v.w;
    float q = v.x * v.x + v.y * v.y + v.z * v.z + v.w * v.w;
#pragma unroll
    for (int o = 16; o > 0; o >>= 1) {
        s += __shfl_xor_sync(0xffffffffu, s, o);
        q += __shfl_xor_sync(0xffffffffu, q, o);
    }
    __shared__ float ss[4], sq[4];
    int w = tid >> 5, l = tid & 31;
    if (l == 0) { ss[w] = s; sq[w] = q; }
    __syncthreads();
    s = ss[0] + ss[1] + ss[2] + ss[3];
    q = sq[0] + sq[1] + sq[2] + sq[3];
    float mean = s * (1.f / CC);
    float var  = q * (1.f / CC) - mean * mean;
    float r = rsqrtf(var + LN_EPS);
    float4 gv = ((const float4*)g)[tid];
    float4 bv = ((const float4*)beta)[tid];
    v.x = (v.x - mean) * r * gv.x + bv.x;
    v.y = (v.y - mean) * r * gv.y + bv.y;
    v.z = (v.z - mean) * r * gv.z + bv.z;
    v.w = (v.w - mean) * r * gv.w + bv.w;
    xr[tid] = v;
}

// ---------------- LN + Linear(C->1) + mask, one block per row ---------------
__global__ void __launch_bounds__(128) ln_lin_kernel(const float* __restrict__ x,
                                                     const float* __restrict__ g,
                                                     const float* __restrict__ beta,
                                                     const float* __restrict__ lw,
                                                     const float* __restrict__ lb,
                                                     const int* __restrict__ lens,
                                                     float* __restrict__ pred)
{
    size_t row = blockIdx.x;
    const float4* xr = (const float4*)(x + row * CC);
    int tid = threadIdx.x;
    float4 v = xr[tid];
    float s = v.x + v.y + v.z + v.w;
    float q = v.x * v.x + v.y * v.y + v.z * v.z + v.w * v.w;
#pragma unroll
    for (int o = 16; o > 0; o >>= 1) {
        s += __shfl_xor_sync(0xffffffffu, s, o);
        q += __shfl_xor_sync(0xffffffffu, q, o);
    }
    __shared__ float ss[4], sq[4], sp[4];
    int w = tid >> 5, l = tid & 31;
    if (l == 0) { ss[w] = s; sq[w] = q; }
    __syncthreads();
    s = ss[0] + ss[1] + ss[2] + ss[3];
    q = sq[0] + sq[1] + sq[2] + sq[3];
    float mean = s * (1.f / CC);
    float var  = q * (1.f / CC) - mean * mean;
    float r = rsqrtf(var + LN_EPS);
    float4 gv = ((const float4*)g)[tid];
    float4 bv = ((const float4*)beta)[tid];
    float4 wv = ((const float4*)lw)[tid];
    float part = ((v.x - mean) * r * gv.x + bv.x) * wv.x
               + ((v.y - mean) * r * gv.y + bv.y) * wv.y
               + ((v.z - mean) * r * gv.z + bv.z) * wv.z
               + ((v.w - mean) * r * gv.w + bv.w) * wv.w;
#pragma unroll
    for (int o = 16; o > 0; o >>= 1)
        part += __shfl_xor_sync(0xffffffffu, part, o);
    if (l == 0) sp[w] = part;
    __syncthreads();
    if (tid == 0) {
        float val = sp[0] + sp[1] + sp[2] + sp[3] + lb[0];
        int b = (int)(row >> 10);
        int t = (int)(row & 1023);
        pred[row] = (t < lens[b]) ? val : 0.f;
    }
}

// ---------------- regulate: per-frame binary search + row copy --------------
__global__ void __launch_bounds__(256) reg_kernel(const float* __restrict__ batch,
                                                  const int* __restrict__ cum,
                                                  float* __restrict__ out)
{
    int b  = blockIdx.y;
    int f0 = blockIdx.x * 32;
    __shared__ int sc[TT];
    int tid = threadIdx.x;
    const int* crow = cum + (size_t)b * TT;
#pragma unroll
    for (int j = 0; j < 4; j++) sc[tid + 256 * j] = crow[tid + 256 * j];
    __syncthreads();
    int total = sc[TT - 1];
    int warp = tid >> 5, lane = tid & 31;
    float* outb = out + (size_t)b * LMAX * CC;
    const float* inb = batch + (size_t)b * TT * CC;
#pragma unroll
    for (int qq = 0; qq < 4; qq++) {
        int f = f0 + warp * 4 + qq;
        float4* dst = (float4*)(outb + (size_t)f * CC);
        if (f < total) {
            int lo = 0, hi = TT;
            while (lo < hi) {
                int mid = (lo + hi) >> 1;
                if (sc[mid] <= f) lo = mid + 1; else hi = mid;
            }
            const float4* src = (const float4*)(inb + (size_t)lo * CC);
#pragma unroll
            for (int u = 0; u < 4; u++) dst[lane + 32 * u] = src[lane + 32 * u];
        } else {
            float4 z = make_float4(0.f, 0.f, 0.f, 0.f);
#pragma unroll
            for (int u = 0; u < 4; u++) dst[lane + 32 * u] = z;
        }
    }
}

// ---------------- launch --------------------------------------------------
extern "C" void kernel_launch(void* const* d_in, const int* in_sizes, int n_in,
                              void* d_out, int out_size)
{
    const float* batch = (const float*)d_in[0];
    const int*   lens  = (const int*)d_in[1];
    const int*   durs  = (const int*)d_in[3];
    const float* w1    = (const float*)d_in[4];
    const float* b1    = (const float*)d_in[5];
    const float* g1    = (const float*)d_in[6];
    const float* be1   = (const float*)d_in[7];
    const float* w2    = (const float*)d_in[8];
    const float* b2    = (const float*)d_in[9];
    const float* g2    = (const float*)d_in[10];
    const float* be2   = (const float*)d_in[11];
    const float* lw    = (const float*)d_in[12];
    const float* lb    = (const float*)d_in[13];

    float* out    = (float*)d_out;
    float* padded = out;
    float* mel    = out + (size_t)BB * LMAX * CC;
    float* pred   = mel + BB;

    float *buf1, *buf2, *wt;
    int   *cum;
    cudaGetSymbolAddress((void**)&buf1, g_buf1);
    cudaGetSymbolAddress((void**)&buf2, g_buf2);
    cudaGetSymbolAddress((void**)&wt,   g_wt);
    cudaGetSymbolAddress((void**)&cum,  g_cum);
    float* wt2 = wt + (size_t)KK * CC * CC;

    wt_kernel<<<(CC * CC + 255) / 256, 256>>>(w1, wt);
    wt_kernel<<<(CC * CC + 255) / 256, 256>>>(w2, wt2);
    dur_kernel<<<BB, 256>>>(durs, lens, cum, mel);

    dim3 gg(BT / BM, CC / BN);
    conv_mma_kernel<<<gg, 256>>>(batch, wt, b1, buf1);
    ln_kernel<<<BT, 128>>>(buf1, g1, be1);
    conv_mma_kernel<<<gg, 256>>>(buf1, wt2, b2, buf2);
    ln_lin_kernel<<<BT, 128>>>(buf2, g2, be2, lw, lb, lens, pred);

    reg_kernel<<<dim3(LMAX / 32, BB), 256>>>(batch, cum, padded);
}

// round 5
// speedup vs baseline: 3.3547x; 1.0687x over previous
#include <cuda_runtime.h>
#include <cstdint>
#include <cstddef>

// Problem constants
#define BB   32
#define TT   1024
#define CC   512
#define KK   3
#define LMAX 4096
#define BT   (BB*TT)
#define LN_EPS 1e-5f

// GEMM tiling (tf32 mma.sync m16n8k8)
#define BM 128
#define BN 128
#define BK 16
#define NSLAB ((KK*CC)/BK)    // 96

// ---------------- scratch (device globals; no allocations allowed) ----------
__device__ float g_bufA[(size_t)BT * CC];          // tf32-rounded batch (conv1 A)
__device__ float g_buf1[(size_t)BT * CC];
__device__ float g_buf2[(size_t)BT * CC];
__device__ float g_wt[2 * KK * CC * CC];           // [set][k][ci][co], tf32-rounded
__device__ int   g_cum[BB * TT];

// ================= helpers ==================================================
__device__ __forceinline__ uint32_t smem_u32(const void* p) {
    uint32_t r;
    asm("{ .reg .u64 t; cvta.to.shared.u64 t, %1; cvt.u32.u64 %0, t; }"
        : "=r"(r) : "l"(p));
    return r;
}
__device__ __forceinline__ void cp_async16(uint32_t dst, const void* src, bool ok) {
    int sz = ok ? 16 : 0;
    asm volatile("cp.async.ca.shared.global [%0], [%1], 16, %2;"
                 :: "r"(dst), "l"(src), "r"(sz));
}
#define CP_COMMIT() asm volatile("cp.async.commit_group;" ::: "memory")
#define CP_WAIT1()  asm volatile("cp.async.wait_group 1;" ::: "memory")
#define CP_WAIT0()  asm volatile("cp.async.wait_group 0;" ::: "memory")

__device__ __forceinline__ float f_rna_tf32(float f) {
    uint32_t u;
    asm("cvt.rna.tf32.f32 %0, %1;" : "=r"(u) : "f"(f));
    return __uint_as_float(u);
}
__device__ __forceinline__ void mma_tf32(float* c, const uint32_t* a, const uint32_t* b) {
    asm volatile("mma.sync.aligned.m16n8k8.row.col.f32.tf32.tf32.f32 "
                 "{%0,%1,%2,%3}, {%4,%5,%6,%7}, {%8,%9}, {%0,%1,%2,%3};"
                 : "+f"(c[0]), "+f"(c[1]), "+f"(c[2]), "+f"(c[3])
                 : "r"(a[0]), "r"(a[1]), "r"(a[2]), "r"(a[3]),
                   "r"(b[0]), "r"(b[1]));
}

// ---------------- tf32 pre-round copy (batch -> g_bufA) --------------------
__global__ void __launch_bounds__(256) round_kernel(const float4* __restrict__ in,
                                                    float4* __restrict__ out)
{
    size_t i = (size_t)blockIdx.x * 256 + threadIdx.x;   // over BT*CC/4
    float4 v = in[i];
    v.x = f_rna_tf32(v.x);
    v.y = f_rna_tf32(v.y);
    v.z = f_rna_tf32(v.z);
    v.w = f_rna_tf32(v.w);
    out[i] = v;
}

// ---------------- weight transpose + tf32 round: w[co][ci][k] -> wt[k][ci][co]
__global__ void __launch_bounds__(256) wt_kernel(const float* __restrict__ w,
                                                 float* __restrict__ wt)
{
    int idx = blockIdx.x * 256 + threadIdx.x;
    if (idx >= CC * CC) return;
    int co = idx >> 9;
    int ci = idx & (CC - 1);
#pragma unroll
    for (int k = 0; k < KK; k++)
        wt[((size_t)k * CC + ci) * CC + co] = f_rna_tf32(w[((size_t)co * CC + ci) * KK + k]);
}

// ---------------- durations: mask, total==0 fallback, inclusive scan --------
__global__ void __launch_bounds__(256) dur_kernel(const int* __restrict__ durs,
                                                  const int* __restrict__ lens,
                                                  int* __restrict__ cum,
                                                  float* __restrict__ mel)
{
    int b   = blockIdx.x;
    int len = lens[b];
    int tid = threadIdx.x;
    int base = tid * 4;
    const int* drow = durs + (size_t)b * TT;

    int d[4];
#pragma unroll
    for (int j = 0; j < 4; j++)
        d[j] = (base + j < len) ? drow[base + j] : 0;
    int ls = d[0] + d[1] + d[2] + d[3];

    __shared__ int sred[256];
    sred[tid] = ls;
    __syncthreads();
    for (int o = 128; o > 0; o >>= 1) {
        if (tid < o) sred[tid] += sred[tid + o];
        __syncthreads();
    }
    int total = sred[0];
    __syncthreads();

    if (total == 0) {
#pragma unroll
        for (int j = 0; j < 4; j++)
            d[j] = (base + j < len) ? 1 : 0;
        ls = d[0] + d[1] + d[2] + d[3];
    }

    __shared__ int sscan[256];
    sscan[tid] = ls;
    __syncthreads();
    for (int o = 1; o < 256; o <<= 1) {
        int v = (tid >= o) ? sscan[tid - o] : 0;
        __syncthreads();
        sscan[tid] += v;
        __syncthreads();
    }
    int c = sscan[tid] - ls;
#pragma unroll
    for (int j = 0; j < 4; j++) {
        c += d[j];
        cum[(size_t)b * TT + base + j] = c;
    }
    if (tid == 255) mel[b] = (float)c;
}

// ---------------- conv-as-GEMM on tf32 mma.sync (pre-rounded inputs) --------
// out[m,n] = relu(sum_k sum_ci A[m+k-1,ci] * Wt[k][ci][n] + bias[n])
__global__ void __launch_bounds__(256, 2) conv_mma_kernel(const float* __restrict__ A,
                                                          const float* __restrict__ Wt,
                                                          const float* __restrict__ bias,
                                                          float* __restrict__ out)
{
    __shared__ float As[2][BM][20];    // pad 20: conflict-free frag loads
    __shared__ float Bs[2][BK][136];   // pad 136 (mod32=8): conflict-free frag loads

    int tid  = threadIdx.x;
    int wid  = tid >> 5;
    int lane = tid & 31;
    int warp_m = wid & 1;        // 2 warps in M (64 rows each)
    int warp_n = wid >> 1;       // 4 warps in N (32 cols each)
    int gid = lane >> 2;         // 0..7
    int tig = lane & 3;          // 0..3

    int m0 = blockIdx.x * BM;
    int b  = m0 >> 10;
    int t0 = m0 & 1023;
    int n0 = blockIdx.y * BN;
    const float* Ab = A + (size_t)b * TT * CC;

    // loader lanes
    int ar = tid >> 2;           // 0..63 (rows ar, ar+64)
    int ac = (tid & 3) * 4;      // 0,4,8,12
    int br = tid >> 5;           // 0..7  (rows br, br+8)
    int bc = (tid & 31) * 4;     // 0..124

    float c[4][4][4];
#pragma unroll
    for (int mt = 0; mt < 4; mt++)
#pragma unroll
        for (int nt = 0; nt < 4; nt++)
#pragma unroll
            for (int q = 0; q < 4; q++) c[mt][nt][q] = 0.f;

    auto load_slab = [&](int s, int buf) {
        int k   = s >> 5;              // conv tap 0..2 (32 slabs each)
        int ci0 = (s & 31) * BK;       // 0..496
#pragma unroll
        for (int h = 0; h < 2; h++) {
            int r = ar + h * 64;
            int strow = t0 + r + k - 1;
            bool ok = (strow >= 0 && strow < TT);
            const float* src = Ab + (ok ? (size_t)strow * CC : 0) + ci0 + ac;
            cp_async16(smem_u32(&As[buf][r][ac]), src, ok);
        }
#pragma unroll
        for (int h = 0; h < 2; h++) {
            int r = br + h * 8;
            const float* src = Wt + ((size_t)k * CC + ci0 + r) * CC + n0 + bc;
            cp_async16(smem_u32(&Bs[buf][r][bc]), src, true);
        }
    };

    load_slab(0, 0);
    CP_COMMIT();

    for (int s = 0; s < NSLAB; s++) {
        int buf = s & 1;
        if (s + 1 < NSLAB) {
            load_slab(s + 1, buf ^ 1);
            CP_COMMIT();
            CP_WAIT1();
        } else {
            CP_WAIT0();
        }
        __syncthreads();

#pragma unroll
        for (int kk = 0; kk < BK; kk += 8) {
            uint32_t af[4][4];
#pragma unroll
            for (int mt = 0; mt < 4; mt++) {
                int mr = warp_m * 64 + mt * 16;
                af[mt][0] = __float_as_uint(As[buf][mr + gid    ][kk + tig    ]);
                af[mt][1] = __float_as_uint(As[buf][mr + gid + 8][kk + tig    ]);
                af[mt][2] = __float_as_uint(As[buf][mr + gid    ][kk + tig + 4]);
                af[mt][3] = __float_as_uint(As[buf][mr + gid + 8][kk + tig + 4]);
            }
            uint32_t bf[4][2];
#pragma unroll
            for (int nt = 0; nt < 4; nt++) {
                int nc = warp_n * 32 + nt * 8 + gid;
                bf[nt][0] = __float_as_uint(Bs[buf][kk + tig    ][nc]);
                bf[nt][1] = __float_as_uint(Bs[buf][kk + tig + 4][nc]);
            }
#pragma unroll
            for (int mt = 0; mt < 4; mt++)
#pragma unroll
                for (int nt = 0; nt < 4; nt++)
                    mma_tf32(c[mt][nt], af[mt], bf[nt]);
        }
        __syncthreads();
    }

    // ---- epilogue: bias + relu, coalesced-quad stores ----
#pragma unroll
    for (int mt = 0; mt < 4; mt++) {
        int row = m0 + warp_m * 64 + mt * 16 + gid;
#pragma unroll
        for (int nt = 0; nt < 4; nt++) {
            int col = n0 + warp_n * 32 + nt * 8 + tig * 2;
            float b0 = __ldg(&bias[col]);
            float b1 = __ldg(&bias[col + 1]);
            float2 v0, v1;
            v0.x = fmaxf(c[mt][nt][0] + b0, 0.f);
            v0.y = fmaxf(c[mt][nt][1] + b1, 0.f);
            v1.x = fmaxf(c[mt][nt][2] + b0, 0.f);
            v1.y = fmaxf(c[mt][nt][3] + b1, 0.f);
            *(float2*)&out[(size_t)row * CC + col]       = v0;
            *(float2*)&out[(size_t)(row + 8) * CC + col] = v1;
        }
    }
}

// ---------------- LayerNorm over C=512, in-place, one block per row ---------
// Stores tf32-rounded values (input to conv2; identical numerics to in-loop cvt)
__global__ void __launch_bounds__(128) ln_kernel(float* __restrict__ x,
                                                 const float* __restrict__ g,
                                                 const float* __restrict__ beta)
{
    size_t row = blockIdx.x;
    float4* xr = (float4*)(x + row * CC);
    int tid = threadIdx.x;
    float4 v = xr[tid];
    float s = v.x + v.y + v.z + v.w;
    float q = v.x * v.x + v.y * v.y + v.z * v.z + v.w * v.w;
#pragma unroll
    for (int o = 16; o > 0; o >>= 1) {
        s += __shfl_xor_sync(0xffffffffu, s, o);
        q += __shfl_xor_sync(0xffffffffu, q, o);
    }
    __shared__ float ss[4], sq[4];
    int w = tid >> 5, l = tid & 31;
    if (l == 0) { ss[w] = s; sq[w] = q; }
    __syncthreads();
    s = ss[0] + ss[1] + ss[2] + ss[3];
    q = sq[0] + sq[1] + sq[2] + sq[3];
    float mean = s * (1.f / CC);
    float var  = q * (1.f / CC) - mean * mean;
    float r = rsqrtf(var + LN_EPS);
    float4 gv = ((const float4*)g)[tid];
    float4 bv = ((const float4*)beta)[tid];
    v.x = f_rna_tf32((v.x - mean) * r * gv.x + bv.x);
    v.y = f_rna_tf32((v.y - mean) * r * gv.y + bv.y);
    v.z = f_rna_tf32((v.z - mean) * r * gv.z + bv.z);
    v.w = f_rna_tf32((v.w - mean) * r * gv.w + bv.w);
    xr[tid] = v;
}

// ---------------- LN + Linear(C->1) + mask, one block per row ---------------
__global__ void __launch_bounds__(128) ln_lin_kernel(const float* __restrict__ x,
                                                     const float* __restrict__ g,
                                                     const float* __restrict__ beta,
                                                     const float* __restrict__ lw,
                                                     const float* __restrict__ lb,
                                                     const int* __restrict__ lens,
                                                     float* __restrict__ pred)
{
    size_t row = blockIdx.x;
    const float4* xr = (const float4*)(x + row * CC);
    int tid = threadIdx.x;
    float4 v = xr[tid];
    float s = v.x + v.y + v.z + v.w;
    float q = v.x * v.x + v.y * v.y + v.z * v.z + v.w * v.w;
#pragma unroll
    for (int o = 16; o > 0; o >>= 1) {
        s += __shfl_xor_sync(0xffffffffu, s, o);
        q += __shfl_xor_sync(0xffffffffu, q, o);
    }
    __shared__ float ss[4], sq[4], sp[4];
    int w = tid >> 5, l = tid & 31;
    if (l == 0) { ss[w] = s; sq[w] = q; }
    __syncthreads();
    s = ss[0] + ss[1] + ss[2] + ss[3];
    q = sq[0] + sq[1] + sq[2] + sq[3];
    float mean = s * (1.f / CC);
    float var  = q * (1.f / CC) - mean * mean;
    float r = rsqrtf(var + LN_EPS);
    float4 gv = ((const float4*)g)[tid];
    float4 bv = ((const float4*)beta)[tid];
    float4 wv = ((const float4*)lw)[tid];
    float part = ((v.x - mean) * r * gv.x + bv.x) * wv.x
               + ((v.y - mean) * r * gv.y + bv.y) * wv.y
               + ((v.z - mean) * r * gv.z + bv.z) * wv.z
               + ((v.w - mean) * r * gv.w + bv.w) * wv.w;
#pragma unroll
    for (int o = 16; o > 0; o >>= 1)
        part += __shfl_xor_sync(0xffffffffu, part, o);
    if (l == 0) sp[w] = part;
    __syncthreads();
    if (tid == 0) {
        float val = sp[0] + sp[1] + sp[2] + sp[3] + lb[0];
        int b = (int)(row >> 10);
        int t = (int)(row & 1023);
        pred[row] = (t < lens[b]) ? val : 0.f;
    }
}

// ---------------- regulate: per-frame binary search + row copy --------------
__global__ void __launch_bounds__(256) reg_kernel(const float* __restrict__ batch,
                                                  const int* __restrict__ cum,
                                                  float* __restrict__ out)
{
    int b  = blockIdx.y;
    int f0 = blockIdx.x * 32;
    __shared__ int sc[TT];
    int tid = threadIdx.x;
    const int* crow = cum + (size_t)b * TT;
#pragma unroll
    for (int j = 0; j < 4; j++) sc[tid + 256 * j] = crow[tid + 256 * j];
    __syncthreads();
    int total = sc[TT - 1];
    int warp = tid >> 5, lane = tid & 31;
    float* outb = out + (size_t)b * LMAX * CC;
    const float* inb = batch + (size_t)b * TT * CC;
#pragma unroll
    for (int qq = 0; qq < 4; qq++) {
        int f = f0 + warp * 4 + qq;
        float4* dst = (float4*)(outb + (size_t)f * CC);
        if (f < total) {
            int lo = 0, hi = TT;
            while (lo < hi) {
                int mid = (lo + hi) >> 1;
                if (sc[mid] <= f) lo = mid + 1; else hi = mid;
            }
            const float4* src = (const float4*)(inb + (size_t)lo * CC);
#pragma unroll
            for (int u = 0; u < 4; u++) dst[lane + 32 * u] = src[lane + 32 * u];
        } else {
            float4 z = make_float4(0.f, 0.f, 0.f, 0.f);
#pragma unroll
            for (int u = 0; u < 4; u++) dst[lane + 32 * u] = z;
        }
    }
}

// ---------------- launch --------------------------------------------------
extern "C" void kernel_launch(void* const* d_in, const int* in_sizes, int n_in,
                              void* d_out, int out_size)
{
    const float* batch = (const float*)d_in[0];
    const int*   lens  = (const int*)d_in[1];
    const int*   durs  = (const int*)d_in[3];
    const float* w1    = (const float*)d_in[4];
    const float* b1    = (const float*)d_in[5];
    const float* g1    = (const float*)d_in[6];
    const float* be1   = (const float*)d_in[7];
    const float* w2    = (const float*)d_in[8];
    const float* b2    = (const float*)d_in[9];
    const float* g2    = (const float*)d_in[10];
    const float* be2   = (const float*)d_in[11];
    const float* lw    = (const float*)d_in[12];
    const float* lb    = (const float*)d_in[13];

    float* out    = (float*)d_out;
    float* padded = out;
    float* mel    = out + (size_t)BB * LMAX * CC;
    float* pred   = mel + BB;

    float *bufA, *buf1, *buf2, *wt;
    int   *cum;
    cudaGetSymbolAddress((void**)&bufA, g_bufA);
    cudaGetSymbolAddress((void**)&buf1, g_buf1);
    cudaGetSymbolAddress((void**)&buf2, g_buf2);
    cudaGetSymbolAddress((void**)&wt,   g_wt);
    cudaGetSymbolAddress((void**)&cum,  g_cum);
    float* wt2 = wt + (size_t)KK * CC * CC;

    wt_kernel<<<(CC * CC + 255) / 256, 256>>>(w1, wt);
    wt_kernel<<<(CC * CC + 255) / 256, 256>>>(w2, wt2);
    dur_kernel<<<BB, 256>>>(durs, lens, cum, mel);
    round_kernel<<<(BT * (CC / 4)) / 256, 256>>>((const float4*)batch, (float4*)bufA);

    dim3 gg(BT / BM, CC / BN);
    conv_mma_kernel<<<gg, 256>>>(bufA, wt, b1, buf1);
    ln_kernel<<<BT, 128>>>(buf1, g1, be1);
    conv_mma_kernel<<<gg, 256>>>(buf1, wt2, b2, buf2);
    ln_lin_kernel<<<BT, 128>>>(buf2, g2, be2, lw, lb, lens, pred);

    reg_kernel<<<dim3(LMAX / 32, BB), 256>>>(batch, cum, padded);
}